// round 2
// baseline (speedup 1.0000x reference)
#include <cuda_runtime.h>

#define BB 4
#define SS 2048
#define DD 16
#define HH 16
#define NPAIR (BB*HH)      // 64
#define TQ 128
#define NT (SS/TQ)         // 16

typedef unsigned long long ull;

// Scratch
__device__ float g_q[NPAIR*SS];   // q * log2(e), [pair][s]
__device__ float g_k[NPAIR*SS];
__device__ float g_v[NPAIR*SS];
__device__ float g_o[BB*SS*DD];   // attn out, [b][s][h]

__device__ __forceinline__ float ex2f(float x) {
    float r; asm("ex2.approx.ftz.f32 %0, %1;" : "=f"(r) : "f"(x)); return r;
}
__device__ __forceinline__ ull mul2(ull a, ull b) {
    ull d; asm("mul.rn.f32x2 %0, %1, %2;" : "=l"(d) : "l"(a), "l"(b)); return d;
}
__device__ __forceinline__ ull add2(ull a, ull b) {
    ull d; asm("add.rn.f32x2 %0, %1, %2;" : "=l"(d) : "l"(a), "l"(b)); return d;
}
__device__ __forceinline__ ull fma2(ull a, ull b, ull c) {
    ull d; asm("fma.rn.f32x2 %0, %1, %2, %3;" : "=l"(d) : "l"(a), "l"(b), "l"(c)); return d;
}
__device__ __forceinline__ ull pack2(float a, float b) {
    ull d; asm("mov.b64 %0, {%1, %2};" : "=l"(d) : "f"(a), "f"(b)); return d;
}
union UF2 { ull u; float2 f; unsigned int i[2]; };
__device__ __forceinline__ float2 lohi(ull a) { UF2 t; t.u = a; return t.f; }
__device__ __forceinline__ ull asu(float2 a)  { UF2 t; t.f = a; return t.u; }

// ---------------------------------------------------------------------------
// Kernel 1: qkv projection. Block = 16 rows x 16 cols of x (256 contiguous
// elements); each thread produces q,k,v for one (row, h).
// ---------------------------------------------------------------------------
__global__ void __launch_bounds__(256) qkv_kernel(
    const float* __restrict__ x, const float* __restrict__ w,
    const float* __restrict__ bqkv)
{
    __shared__ float sx[16 * 17];      // padded rows
    __shared__ float sw[16 * 48];
    __shared__ float sb[48];
    int tid = threadIdx.x;
    {
        int r = tid >> 4, d = tid & 15;
        sx[r * 17 + d] = x[blockIdx.x * 256 + tid];
    }
    for (int i = tid; i < 16 * 48; i += 256) sw[i] = w[i];
    if (tid < 48) sb[tid] = bqkv[tid];
    __syncthreads();

    int sl = tid & 15;           // local row (s within tile)
    int c  = tid >> 4;           // head 0..15
    int row = blockIdx.x * 16 + sl;
    int b = row >> 11, s = row & (SS - 1);

    float aq = sb[c], ak = sb[c + 16], av = sb[c + 32];
    #pragma unroll
    for (int d = 0; d < 16; ++d) {
        float xv = sx[sl * 17 + d];
        aq = fmaf(xv, sw[d * 48 + c],      aq);
        ak = fmaf(xv, sw[d * 48 + c + 16], ak);
        av = fmaf(xv, sw[d * 48 + c + 32], av);
    }
    int idx = (b * HH + c) * SS + s;
    g_q[idx] = aq * 1.44269504088896340736f;  // scale=1, fold log2(e)
    g_k[idx] = ak;
    g_v[idx] = av;
}

// ---------------------------------------------------------------------------
// Kernel 2: causal scalar-head attention, hybrid MUFU + FFMA-poly exp2.
// ---------------------------------------------------------------------------
__global__ void __launch_bounds__(128) attn_kernel()
{
    __shared__ float sk[SS];
    __shared__ float sv[SS];

    int bx   = blockIdx.x;
    int pair = bx & (NPAIR - 1);
    int tile = NT - 1 - (bx >> 6);          // heavy-first
    int tile_start = tile * TQ;
    int tile_end   = tile_start + TQ;

    const float* __restrict__ gk = g_k + pair * SS;
    const float* __restrict__ gv = g_v + pair * SS;
    for (int j = threadIdx.x; j < tile_end; j += TQ) {
        sk[j] = gk[j];
        sv[j] = gv[j];
    }
    __syncthreads();

    int   i  = tile_start + threadIdx.x;
    float qi = g_q[pair * SS + i];
    ull   q2 = pack2(qi, qi);

    // poly exp2 constants (packed)
    const ull C2  = pack2(12582912.0f, 12582912.0f);    // 1.5 * 2^23
    const ull nC2 = pack2(-12582912.0f, -12582912.0f);
    const ull M1  = pack2(-1.0f, -1.0f);
    const ull P5  = pack2(0.0013333558f, 0.0013333558f);
    const ull P4  = pack2(0.0096181291f, 0.0096181291f);
    const ull P3  = pack2(0.0555041087f, 0.0555041087f);
    const ull P2  = pack2(0.2402265069f, 0.2402265069f);
    const ull P1  = pack2(0.6931471806f, 0.6931471806f);
    const ull P0  = pack2(1.0f, 1.0f);

    ull den01 = 0, den23 = 0, den45 = 0, denP = 0;
    ull num01 = 0, num23 = 0, num45 = 0, numP = 0;

    // Phase 1: uniform prefix (all j < tile_start <= i). 8 exps/iter:
    // 6 via MUFU (binding pipe), 2 via FFMA/ALU polynomial.
    const float2* skp = reinterpret_cast<const float2*>(sk);
    const float2* svp = reinterpret_cast<const float2*>(sv);
    for (int j4 = 0; j4 < (tile_start >> 1); j4 += 4) {
        ull K01 = asu(skp[j4]),     K23 = asu(skp[j4 + 1]);
        ull K45 = asu(skp[j4 + 2]), K67 = asu(skp[j4 + 3]);
        ull V01 = asu(svp[j4]),     V23 = asu(svp[j4 + 1]);
        ull V45 = asu(svp[j4 + 2]), V67 = asu(svp[j4 + 3]);

        ull t01 = mul2(q2, K01), t23 = mul2(q2, K23);
        ull t45 = mul2(q2, K45), t67 = mul2(q2, K67);

        // MUFU path: j, j+1 .. j+5
        float2 T01 = lohi(t01), T23 = lohi(t23), T45 = lohi(t45);
        ull E01 = pack2(ex2f(T01.x), ex2f(T01.y));
        ull E23 = pack2(ex2f(T23.x), ex2f(T23.y));
        ull E45 = pack2(ex2f(T45.x), ex2f(T45.y));
        den01 = add2(den01, E01);  num01 = fma2(E01, V01, num01);
        den23 = add2(den23, E23);  num23 = fma2(E23, V23, num23);
        den45 = add2(den45, E45);  num45 = fma2(E45, V45, num45);

        // Poly path: j+6, j+7.  exp2(t) = 2^round(t) * poly(t - round(t))
        ull z  = add2(t67, C2);            // round-to-int in mantissa
        ull zc = add2(z, nC2);             // round(t) as float
        ull r  = fma2(zc, M1, t67);        // frac in [-0.5, 0.5]
        ull p  = fma2(r, P5, P4);
        p = fma2(r, p, P3);
        p = fma2(r, p, P2);
        p = fma2(r, p, P1);
        p = fma2(r, p, P0);
        UF2 zu; zu.u = z;
        UF2 pu; pu.u = p;
        unsigned int b0 = pu.i[0] + (zu.i[0] << 23);
        unsigned int b1 = pu.i[1] + (zu.i[1] << 23);
        UF2 e; e.i[0] = b0; e.i[1] = b1;
        denP = add2(denP, e.u);  numP = fma2(e.u, V67, numP);
    }

    float2 d01 = lohi(den01), d23 = lohi(den23), d45 = lohi(den45), dP = lohi(denP);
    float2 n01 = lohi(num01), n23 = lohi(num23), n45 = lohi(num45), nP = lohi(numP);
    float den = ((d01.x + d01.y) + (d23.x + d23.y)) + ((d45.x + d45.y) + (dP.x + dP.y));
    float num = ((n01.x + n01.y) + (n23.x + n23.y)) + ((n45.x + n45.y) + (nP.x + nP.y));

    // Phase 2: ragged diagonal block, j in [tile_start, i], MUFU only.
    float den2 = 0.f, num2 = 0.f;
    for (int j = tile_start; j <= i; ++j) {
        float e = ex2f(qi * sk[j]);
        den2 += e;
        num2 = fmaf(e, sv[j], num2);
    }
    den += den2; num += num2;

    int b = pair >> 4, h = pair & 15;
    g_o[(b * SS + i) * DD + h] = num / den;
}

// ---------------------------------------------------------------------------
// Kernel 3: output projection. Block = 16 rows x 16 cols (256 contiguous).
// ---------------------------------------------------------------------------
__global__ void __launch_bounds__(256) proj_kernel(
    const float* __restrict__ w, const float* __restrict__ bo,
    float* __restrict__ out)
{
    __shared__ float so[16 * 17];
    __shared__ float sw[16 * 16];
    __shared__ float sb[16];
    int tid = threadIdx.x;
    {
        int r = tid >> 4, d = tid & 15;
        so[r * 17 + d] = g_o[blockIdx.x * 256 + tid];
    }
    if (tid < 256) sw[tid] = w[tid];
    if (tid < 16)  sb[tid] = bo[tid];
    __syncthreads();

    int sl = tid & 15;       // local row
    int c  = tid >> 4;       // out col
    float acc = sb[c];
    #pragma unroll
    for (int d = 0; d < 16; ++d)
        acc = fmaf(so[sl * 17 + d], sw[d * 16 + c], acc);

    // out[blockIdx*256 + sl*16 + c]
    out[blockIdx.x * 256 + sl * 16 + c] = acc;
}

// ---------------------------------------------------------------------------
extern "C" void kernel_launch(void* const* d_in, const int* in_sizes, int n_in,
                              void* d_out, int out_size)
{
    const float* x     = (const float*)d_in[0];
    const float* w_qkv = (const float*)d_in[1];
    const float* b_qkv = (const float*)d_in[2];
    const float* w_out = (const float*)d_in[3];
    const float* b_out = (const float*)d_in[4];
    float* out = (float*)d_out;

    qkv_kernel<<<(BB * SS * DD) / 256, 256>>>(x, w_qkv, b_qkv);
    attn_kernel<<<NPAIR * NT, TQ>>>();
    proj_kernel<<<(BB * SS * DD) / 256, 256>>>(w_out, b_out, out);
}

// round 5
// speedup vs baseline: 1.5627x; 1.5627x over previous
#include <cuda_runtime.h>

#define BB 4
#define SS 2048
#define HH 16
#define NPAIR 64
#define NB 512                 // grid size (64 pairs x 8 tiles)
#define L2E 1.44269504088896340736f

typedef unsigned long long ull;

// Scratch (device globals; no allocation allowed).
__device__ float  g_q [NPAIR*SS];     // q * log2(e), [pair][s]
__device__ float2 g_kv[NPAIR*SS];     // (k,v) interleaved, [pair][s]
__device__ float  g_o [BB*SS*HH];     // attn out, [b][s][h]
__device__ unsigned int g_cnt[2] = {0, 0};
__device__ unsigned int g_gen[2] = {0, 0};   // monotonically increasing generations

__device__ __forceinline__ float ex2f(float x) {
    float r; asm("ex2.approx.ftz.f32 %0, %1;" : "=f"(r) : "f"(x)); return r;
}
__device__ __forceinline__ ull mul2(ull a, ull b) {
    ull d; asm("mul.rn.f32x2 %0, %1, %2;" : "=l"(d) : "l"(a), "l"(b)); return d;
}
__device__ __forceinline__ ull add2(ull a, ull b) {
    ull d; asm("add.rn.f32x2 %0, %1, %2;" : "=l"(d) : "l"(a), "l"(b)); return d;
}
__device__ __forceinline__ ull fma2(ull a, ull b, ull c) {
    ull d; asm("fma.rn.f32x2 %0, %1, %2, %3;" : "=l"(d) : "l"(a), "l"(b), "l"(c)); return d;
}
__device__ __forceinline__ ull pack2(float a, float b) {
    ull d; asm("mov.b64 %0, {%1, %2};" : "=l"(d) : "f"(a), "f"(b)); return d;
}
__device__ __forceinline__ void unpack2(ull a, float& x, float& y) {
    asm("mov.b64 {%0, %1}, %2;" : "=f"(x), "=f"(y) : "l"(a));
}

// Software grid barrier. All NB blocks are co-resident by construction:
// 148 SMs x 4 blocks/SM (128 thr, 16KB smem, launch_bounds(128,4)) = 592 >= 512.
__device__ __forceinline__ void gbar(int k) {
    __syncthreads();
    if (threadIdx.x == 0) {
        __threadfence();
        unsigned int g = *(volatile unsigned int*)&g_gen[k];
        if (atomicAdd(&g_cnt[k], 1) == NB - 1) {
            g_cnt[k] = 0;
            __threadfence();
            atomicAdd(&g_gen[k], 1);
        } else {
            while (*(volatile unsigned int*)&g_gen[k] == g) __nanosleep(32);
        }
        __threadfence();
    }
    __syncthreads();
}

__global__ void __launch_bounds__(128, 4) fused_kernel(
    const float* __restrict__ x,   // [8192, 16]
    const float* __restrict__ wq,  // [16, 48]
    const float* __restrict__ bq,  // [48]
    const float* __restrict__ wo,  // [16, 16]
    const float* __restrict__ bo,  // [16]
    float* __restrict__ out)       // [8192, 16]
{
    __shared__ float2 skv[SS];     // 16 KB
    int t  = threadIdx.x;
    int bx = blockIdx.x;

    // ---------------- Phase A: qkv projection -----------------------------
    // Block handles 16 rows (bx*16..+15); thread = (row, 6-col group).
    {
        int r  = bx * 16 + (t & 15);
        int cg = t >> 4;                        // 0..7 -> cols cg*6..cg*6+5
        const float4* xr = reinterpret_cast<const float4*>(x + r * 16);
        float4 x0 = xr[0], x1 = xr[1], x2 = xr[2], x3 = xr[3];
        float xv[16] = { x0.x, x0.y, x0.z, x0.w, x1.x, x1.y, x1.z, x1.w,
                         x2.x, x2.y, x2.z, x2.w, x3.x, x3.y, x3.z, x3.w };
        int b = r >> 11, s = r & (SS - 1);
        #pragma unroll
        for (int u = 0; u < 6; ++u) {
            int c = cg * 6 + u;
            float acc = bq[c];
            #pragma unroll
            for (int d = 0; d < 16; ++d) acc = fmaf(xv[d], wq[d * 48 + c], acc);
            int h   = c & 15;
            int idx = (b * HH + h) * SS + s;
            if (c < 16)      g_q[idx]    = acc * L2E;
            else if (c < 32) g_kv[idx].x = acc;
            else             g_kv[idx].y = acc;
        }
    }
    gbar(0);

    // ---------------- Phase B: causal attention (Q=2 per thread) ----------
    {
        int pair = bx & (NPAIR - 1);
        int tile = 7 - (bx >> 6);               // heavy tiles on low bids
        int ts   = tile << 8;                   // tile * 256

        // Stage (k,v) prefix [0, ts+256) in smem.
        {
            const float4* src = reinterpret_cast<const float4*>(g_kv + pair * SS);
            float4* dst = reinterpret_cast<float4*>(skv);
            int n4 = (ts + 256) >> 1;
            for (int j = t; j < n4; j += 128) dst[j] = src[j];
        }
        __syncthreads();

        float q1 = g_q[pair * SS + ts + t];         // query i1 = ts+t
        float q2 = g_q[pair * SS + ts + 128 + t];   // query i2 = i1+128
        ull q12 = pack2(q1, q2);

        const ull MAGIC  = pack2( 12582912.f,  12582912.f);   // 1.5*2^23
        const ull NMAGIC = pack2(-12582912.f, -12582912.f);
        const ull CM1    = pack2(-1.f, -1.f);
        const ull CP5 = pack2(0.0013333558f, 0.0013333558f);
        const ull CP4 = pack2(0.0096181291f, 0.0096181291f);
        const ull CP3 = pack2(0.0555041087f, 0.0555041087f);
        const ull CP2 = pack2(0.2402265069f, 0.2402265069f);
        const ull CP1 = pack2(0.6931471806f, 0.6931471806f);
        const ull CP0 = pack2(1.0f, 1.0f);

        float d1a = 0.f, d1b = 0.f, n1a = 0.f, n1b = 0.f;
        float d2a = 0.f, d2b = 0.f, n2a = 0.f, n2b = 0.f;

        // Uniform prefix: j in [0, ts), both queries. Per 8 j:
        // 7 via MUFU, 1 via f32x2 FFMA polynomial (MUFU 112cyc = FMA 112cyc).
        const float4* s4 = reinterpret_cast<const float4*>(skv);
        #define STEP_M(kk, vv, sfx) {                                          \
            float e1 = ex2f(q1 * (kk));  float e2 = ex2f(q2 * (kk));           \
            d1##sfx += e1;  n1##sfx = fmaf(e1, (vv), n1##sfx);                 \
            d2##sfx += e2;  n2##sfx = fmaf(e2, (vv), n2##sfx); }

        for (int j4 = 0; j4 < (ts >> 1); j4 += 4) {
            float4 A = s4[j4];      // k0 v0 k1 v1
            float4 B = s4[j4 + 1];  // k2 v2 k3 v3
            float4 C = s4[j4 + 2];  // k4 v4 k5 v5
            float4 D = s4[j4 + 3];  // k6 v6 k7 v7

            STEP_M(A.x, A.y, a)
            STEP_M(A.z, A.w, b)
            STEP_M(B.x, B.y, a)
            STEP_M(B.z, B.w, b)
            STEP_M(C.x, C.y, a)
            STEP_M(C.z, C.w, b)
            STEP_M(D.x, D.y, a)
            {   // poly path for k7 = D.z (both queries packed in one f32x2)
                ull kk  = pack2(D.z, D.z);
                ull t12 = mul2(q12, kk);
                ull z   = add2(t12, MAGIC);        // round-to-nearest in mantissa
                ull zc  = add2(z, NMAGIC);         // round(t) as float
                ull rr  = fma2(zc, CM1, t12);      // frac in [-0.5, 0.5]
                ull p   = fma2(rr, CP5, CP4);
                p = fma2(rr, p, CP3);
                p = fma2(rr, p, CP2);
                p = fma2(rr, p, CP1);
                p = fma2(rr, p, CP0);
                float zl, zh, pl, ph;
                unpack2(z, zl, zh);
                unpack2(p, pl, ph);
                float e1 = __uint_as_float(__float_as_uint(pl) + (__float_as_uint(zl) << 23));
                float e2 = __uint_as_float(__float_as_uint(ph) + (__float_as_uint(zh) << 23));
                d1b += e1;  n1b = fmaf(e1, D.w, n1b);
                d2b += e2;  n2b = fmaf(e2, D.w, n2b);
            }
        }

        // Ragged diagonal for q1 (j <= i1 < i2, so also valid for q2).
        int i1 = ts + t;
        #pragma unroll 2
        for (int j = ts; j <= i1; ++j) {
            float2 a = skv[j];
            float e1 = ex2f(q1 * a.x);  d1a += e1;  n1a = fmaf(e1, a.y, n1a);
            float e2 = ex2f(q2 * a.x);  d2a += e2;  n2a = fmaf(e2, a.y, n2a);
        }
        // q2-only segment: exactly 128 iterations (i1+1 .. i1+128 = i2).
        #pragma unroll 4
        for (int jj = 1; jj <= 128; ++jj) {
            float2 a = skv[i1 + jj];
            float e2 = ex2f(q2 * a.x);  d2b += e2;  n2b = fmaf(e2, a.y, n2b);
        }

        int b = pair >> 4, h = pair & 15;
        g_o[(b * SS + ts + t) * HH + h]       = (n1a + n1b) / (d1a + d1b);
        g_o[(b * SS + ts + 128 + t) * HH + h] = (n2a + n2b) / (d2a + d2b);
        #undef STEP_M
    }
    gbar(1);

    // ---------------- Phase C: output projection --------------------------
    {
        #pragma unroll
        for (int u = 0; u < 2; ++u) {
            int idx = bx * 256 + u * 128 + t;    // global output element
            int r = idx >> 4, c = idx & 15;
            const float* orow = g_o + r * 16;
            float acc = bo[c];
            #pragma unroll
            for (int d = 0; d < 16; ++d) acc = fmaf(orow[d], wo[d * 16 + c], acc);
            out[idx] = acc;
        }
    }
}

extern "C" void kernel_launch(void* const* d_in, const int* in_sizes, int n_in,
                              void* d_out, int out_size)
{
    const float* x     = (const float*)d_in[0];
    const float* w_qkv = (const float*)d_in[1];
    const float* b_qkv = (const float*)d_in[2];
    const float* w_out = (const float*)d_in[3];
    const float* b_out = (const float*)d_in[4];
    float* out = (float*)d_out;

    fused_kernel<<<NB, 128>>>(x, w_qkv, b_qkv, w_out, b_out, out);
}